// round 13
// baseline (speedup 1.0000x reference)
#include <cuda_runtime.h>
#include <cuda_fp16.h>
#include <math.h>
#include <stdint.h>

// Problem constants
#define Bc   4
#define Lc   4096
#define Dc   1024
#define Hc   16
#define Dhc  64
#define Mtot (Bc*Lc)        // 16384 rows
#define NC   32             // scan chunks per sequence
#define CHUNK (Lc/NC)       // 128

// GEMM tiling: 128x128 tile, pure fp16 1-term, 2 CTAs/SM
#define MT 128
#define NT 128
#define KT 32               // k per stage
#define NKC (Dc/KT)         // 32 k-chunks
#define TILE_B (MT*KT*2)            // 8192 bytes per operand tile
#define OFF_AH 0
#define OFF_WH (TILE_B)
#define STAGE_BYTES (2*TILE_B)      // 16384
#define NSTAGE 4
#define GEMM_SMEM (NSTAGE*STAGE_BYTES)     // 65536 -> 2 CTAs/SM

// Conflict-free swizzle: 16B-chunk c (0..3) xored with (row>>1)&3.
#define SWZ(row, ch) ((uint32_t)(row) * 64 + (uint32_t)((((ch) ^ (((row) >> 1) & 3)) & 3) * 16))

// ---------------------------------------------------------------------------
// Scratch (__device__ globals per allocation-free rule)
// ---------------------------------------------------------------------------
__device__ __half g_qh[Mtot*Dc];               // q (fp16)
__device__ __half g_vh[Mtot*Dc];               // v (fp16)
__device__ __half g_gh[Mtot*Dc];               // gate pre-activation (fp16)
__device__ __half g_ret[Mtot*Dc];              // ret = q*s (fp16)
__device__ float g_chunkS[Bc*Hc*NC*Dhc];
__device__ float g_carry [Bc*Hc*NC*Dhc];
__device__ __half g_xh[Mtot*Dc];               // x in fp16
__device__ __half g_zh[Mtot*Dc];               // z in fp16
__device__ __half g_wh[4*Dc*Dc];               // Wq,Wv,Wg,Wo in fp16

// ---------------------------------------------------------------------------
// PTX helpers
// ---------------------------------------------------------------------------
__device__ __forceinline__ uint32_t smem_to_u32(const void* p) {
    uint32_t a;
    asm("{ .reg .u64 t; cvta.to.shared.u64 t, %1; cvt.u32.u64 %0, t; }" : "=r"(a) : "l"(p));
    return a;
}

#define CP16(dst, src) \
    asm volatile("cp.async.cg.shared.global [%0], [%1], 16;" :: "r"(dst), "l"(src) : "memory")

__device__ __forceinline__ void ldsm_x4(uint32_t (&r)[4], uint32_t addr) {
    asm volatile("ldmatrix.sync.aligned.m8n8.x4.shared.b16 {%0,%1,%2,%3}, [%4];"
        : "=r"(r[0]), "=r"(r[1]), "=r"(r[2]), "=r"(r[3]) : "r"(addr));
}

__device__ __forceinline__ void mma16816(float (&c)[4], const uint32_t (&a)[4],
                                         uint32_t b0, uint32_t b1) {
    asm volatile("mma.sync.aligned.m16n8k16.row.col.f32.f16.f16.f32 "
        "{%0,%1,%2,%3}, {%4,%5,%6,%7}, {%8,%9}, {%0,%1,%2,%3};"
        : "+f"(c[0]), "+f"(c[1]), "+f"(c[2]), "+f"(c[3])
        : "r"(a[0]), "r"(a[1]), "r"(a[2]), "r"(a[3]), "r"(b0), "r"(b1));
}

// ---------------------------------------------------------------------------
// Batched fp32 -> fp16 convert: x + 4 weights in one launch (grid.y selects)
// ---------------------------------------------------------------------------
struct CvtArgs {
    const float* src[5];
    __half* dst[5];
    int n4[5];
};

__global__ __launch_bounds__(256)
void cvt5_kernel(const CvtArgs args)
{
    const int z = blockIdx.y;
    const float* s = args.src[z];
    __half* d = args.dst[z];
    const int n4 = args.n4[z];

    int i = blockIdx.x * 256 + threadIdx.x;
    if (i >= n4) return;
    float4 f = ((const float4*)s)[i];
    __half2 hp0 = __floats2half2_rn(f.x, f.y);
    __half2 hp1 = __floats2half2_rn(f.z, f.w);
    uint2 hv;
    hv.x = *(uint32_t*)&hp0; hv.y = *(uint32_t*)&hp1;
    ((uint2*)d)[i] = hv;
}

// ---------------------------------------------------------------------------
// mma.sync GEMM: C[m,n] = sum_k A[m,k]*W[n,k], pure fp16, fp32 accum.
// 128x128 CTA tile, 8 warps (32x64 each), K-chunk 32, 4-stage, 2 CTAs/SM.
// ---------------------------------------------------------------------------
template <typename OutT>
struct GemmArgs {
    const __half* Ah;
    const __half* Wh[3];
    OutT* C[3];
};

template <typename OutT>
__global__ __launch_bounds__(256, 2)
void gemm_mma(const GemmArgs<OutT> args)
{
    extern __shared__ char smem[];
    const uint32_t sbase = smem_to_u32(smem);
    const int tid  = threadIdx.x;
    const int lane = tid & 31;
    const int wid  = tid >> 5;
    const int wm   = wid & 3;
    const int wn   = wid >> 2;
    const int bn   = blockIdx.x * NT;
    const int bm   = blockIdx.y * MT;
    const int z    = blockIdx.z;

    const __half* __restrict__ Ah = args.Ah;
    const __half* __restrict__ Wh = args.Wh[z];
    OutT* __restrict__ C = args.C[z];

    const int row0 = tid >> 2;
    const int ch0  = tid & 3;

    auto load_stage = [&](int st, int kc) {
        const uint32_t sb = sbase + (uint32_t)st * STAGE_BYTES;
        const int k0 = kc * KT;
        #pragma unroll
        for (int rep = 0; rep < 2; rep++) {
            int row = row0 + rep * 64;
            uint32_t sw = SWZ(row, ch0);
            const __half* pa = Ah + (size_t)(bm + row) * Dc + k0 + ch0 * 8;
            const __half* pw = Wh + (size_t)(bn + row) * Dc + k0 + ch0 * 8;
            CP16(sb + OFF_AH + sw, pa);
            CP16(sb + OFF_WH + sw, pw);
        }
        asm volatile("cp.async.commit_group;" ::: "memory");
    };

    float c[2][8][4];
    #pragma unroll
    for (int i = 0; i < 2; i++)
        #pragma unroll
        for (int j = 0; j < 8; j++)
            #pragma unroll
            for (int k = 0; k < 4; k++) c[i][j][k] = 0.0f;

    load_stage(0, 0);
    load_stage(1, 1);
    load_stage(2, 2);

    const int a_r  = lane & 15;
    const int a_kc = lane >> 4;
    const int b_r  = ((lane >> 4) << 3) + (lane & 7);
    const int b_kc = (lane >> 3) & 1;

    for (int kc = 0; kc < NKC; kc++) {
        const int st = kc % NSTAGE;
        asm volatile("cp.async.wait_group 2;" ::: "memory");
        __syncthreads();

        if (kc + 3 < NKC) load_stage((kc + 3) % NSTAGE, kc + 3);
        else asm volatile("cp.async.commit_group;" ::: "memory");

        const uint32_t sb = sbase + (uint32_t)st * STAGE_BYTES;

        #pragma unroll
        for (int ks = 0; ks < 2; ks++) {
            uint32_t ah[2][4];
            #pragma unroll
            for (int mi = 0; mi < 2; mi++) {
                int row = wm * 32 + mi * 16 + a_r;
                int kk  = ks * 2 + a_kc;
                ldsm_x4(ah[mi], sb + OFF_AH + SWZ(row, kk));
            }
            uint32_t bh[4][4];
            #pragma unroll
            for (int p = 0; p < 4; p++) {
                int row = wn * 64 + p * 16 + b_r;
                int kk  = ks * 2 + b_kc;
                ldsm_x4(bh[p], sb + OFF_WH + SWZ(row, kk));
            }
            #pragma unroll
            for (int mi = 0; mi < 2; mi++)
                #pragma unroll
                for (int p = 0; p < 4; p++) {
                    int ni = p * 2;
                    mma16816(c[mi][ni+0], ah[mi], bh[p][0], bh[p][1]);
                    mma16816(c[mi][ni+1], ah[mi], bh[p][2], bh[p][3]);
                }
        }
    }

    const int er = lane >> 2;
    const int ec = (lane & 3) * 2;
    #pragma unroll
    for (int mi = 0; mi < 2; mi++) {
        #pragma unroll
        for (int ni = 0; ni < 8; ni++) {
            size_t r0g = (size_t)(bm + wm * 32 + mi * 16 + er);
            size_t cg  = (size_t)(bn + wn * 64 + ni * 8 + ec);
            if constexpr (sizeof(OutT) == 4) {
                float2* p0 = (float2*)((float*)C + r0g * Dc + cg);
                float2* p1 = (float2*)((float*)C + (r0g + 8) * Dc + cg);
                *p0 = make_float2(c[mi][ni][0], c[mi][ni][1]);
                *p1 = make_float2(c[mi][ni][2], c[mi][ni][3]);
            } else {
                __half2 h0 = __floats2half2_rn(c[mi][ni][0], c[mi][ni][1]);
                __half2 h1 = __floats2half2_rn(c[mi][ni][2], c[mi][ni][3]);
                *(__half2*)((__half*)C + r0g * Dc + cg)       = h0;
                *(__half2*)((__half*)C + (r0g + 8) * Dc + cg) = h1;
            }
        }
    }
}

// ---------------------------------------------------------------------------
// Retention scan (fp16 storage, fp32 accumulation)
// ---------------------------------------------------------------------------
__device__ __forceinline__ float lam_of(const float* beta, int h)
{
    float lam = 1.0f - exp2f(-beta[h]);
    lam = fmaxf(lam, 1.17549435e-38f);
    lam = fminf(lam, 1.0f);
    return lam;
}

__global__ __launch_bounds__(64)
void scan_pass1(const __half* __restrict__ v, const float* __restrict__ beta)
{
    int blk = blockIdx.x;
    int cc  = blk % NC;
    int bh  = blk / NC;
    int h   = bh % Hc;
    int b   = bh / Hc;
    int dh  = threadIdx.x;

    float lam = lam_of(beta, h);
    size_t off = ((size_t)(b*Lc + cc*CHUNK)) * Dc + h*Dhc + dh;

    float s = 0.0f;
    #pragma unroll
    for (int t0 = 0; t0 < CHUNK; t0 += 16) {
        __half vals[16];
        #pragma unroll
        for (int j = 0; j < 16; j++)
            vals[j] = v[off + (size_t)j * Dc];
        #pragma unroll
        for (int j = 0; j < 16; j++)
            s = fmaf(lam, s, __half2float(vals[j]));
        off += (size_t)16 * Dc;
    }
    g_chunkS[(size_t)(bh*NC + cc)*Dhc + dh] = s;
}

__global__ __launch_bounds__(256)
void scan_pass2(const float* __restrict__ beta)
{
    int idx = blockIdx.x * blockDim.x + threadIdx.x;  // 0..4095
    int dh  = idx & 63;
    int bh  = idx >> 6;
    int h   = bh & (Hc - 1);

    float lam = lam_of(beta, h);
    float lamP = lam;
    #pragma unroll
    for (int i = 0; i < 7; i++) lamP = lamP * lamP;   // lam^128

    float cs[NC];
    #pragma unroll
    for (int cc = 0; cc < NC; cc++)
        cs[cc] = g_chunkS[(size_t)(bh*NC + cc)*Dhc + dh];

    float carry = 0.0f;
    #pragma unroll
    for (int cc = 0; cc < NC; cc++) {
        g_carry[(size_t)(bh*NC + cc)*Dhc + dh] = carry;
        carry = fmaf(lamP, carry, cs[cc]);
    }
}

__global__ __launch_bounds__(64)
void scan_pass3(const __half* __restrict__ v, const __half* __restrict__ q,
                __half* __restrict__ ret, const float* __restrict__ beta)
{
    int blk = blockIdx.x;
    int cc  = blk % NC;
    int bh  = blk / NC;
    int h   = bh % Hc;
    int b   = bh / Hc;
    int dh  = threadIdx.x;

    float lam = lam_of(beta, h);
    size_t off = ((size_t)(b*Lc + cc*CHUNK)) * Dc + h*Dhc + dh;

    float s = g_carry[(size_t)(bh*NC + cc)*Dhc + dh];
    #pragma unroll
    for (int t0 = 0; t0 < CHUNK; t0 += 8) {
        __half vv[8], qq[8];
        #pragma unroll
        for (int j = 0; j < 8; j++) {
            vv[j] = v[off + (size_t)j * Dc];
            qq[j] = q[off + (size_t)j * Dc];
        }
        #pragma unroll
        for (int j = 0; j < 8; j++) {
            s = fmaf(lam, s, __half2float(vv[j]));
            ret[off + (size_t)j * Dc] = __float2half_rn(__half2float(qq[j]) * s);
        }
        off += (size_t)8 * Dc;
    }
}

// ---------------------------------------------------------------------------
// Fused LayerNorm(ret) * SiLU(gate) -> z fp16 (fp16 in, fp32 reduce)
// ---------------------------------------------------------------------------
__global__ __launch_bounds__(256)
void ln_gate_kernel(const __half* __restrict__ ret, const __half* __restrict__ gate,
                    const float* __restrict__ gamma, const float* __restrict__ lbeta,
                    __half* __restrict__ zh)
{
    const size_t row = blockIdx.x;
    const int tid = threadIdx.x;

    uint2 rv = ((const uint2*)(ret  + row*Dc))[tid];
    uint2 gv = ((const uint2*)(gate + row*Dc))[tid];
    __half2 r01 = *(__half2*)&rv.x, r23 = *(__half2*)&rv.y;
    __half2 g01 = *(__half2*)&gv.x, g23 = *(__half2*)&gv.y;
    float r0 = __half2float(r01.x), r1 = __half2float(r01.y);
    float r2 = __half2float(r23.x), r3 = __half2float(r23.y);
    float g0 = __half2float(g01.x), g1 = __half2float(g01.y);
    float g2 = __half2float(g23.x), g3 = __half2float(g23.y);

    float s  = r0 + r1 + r2 + r3;
    float ss = r0*r0 + r1*r1 + r2*r2 + r3*r3;

    #pragma unroll
    for (int o = 16; o > 0; o >>= 1) {
        s  += __shfl_xor_sync(0xffffffffu, s,  o);
        ss += __shfl_xor_sync(0xffffffffu, ss, o);
    }
    __shared__ float shs[8], shq[8];
    if ((tid & 31) == 0) { shs[tid>>5] = s; shq[tid>>5] = ss; }
    __syncthreads();

    float tot = 0.0f, totq = 0.0f;
    #pragma unroll
    for (int i = 0; i < 8; i++) { tot += shs[i]; totq += shq[i]; }

    const float inv = 1.0f / (float)Dc;
    float mu   = tot * inv;
    float var  = totq * inv - mu * mu;
    float rstd = rsqrtf(var + 1e-5f);

    const float4 gm = ((const float4*)gamma)[tid];
    const float4 bt = ((const float4*)lbeta)[tid];

    float o0 = ((r0 - mu)*rstd*gm.x + bt.x) * (g0 / (1.0f + expf(-g0)));
    float o1 = ((r1 - mu)*rstd*gm.y + bt.y) * (g1 / (1.0f + expf(-g1)));
    float o2 = ((r2 - mu)*rstd*gm.z + bt.z) * (g2 / (1.0f + expf(-g2)));
    float o3 = ((r3 - mu)*rstd*gm.w + bt.w) * (g3 / (1.0f + expf(-g3)));

    __half2 hp0 = __floats2half2_rn(o0, o1);
    __half2 hp1 = __floats2half2_rn(o2, o3);
    uint2 hv;
    hv.x = *(uint32_t*)&hp0; hv.y = *(uint32_t*)&hp1;
    ((uint2*)(zh + row*Dc))[tid] = hv;
}

// ---------------------------------------------------------------------------
// Launch
// ---------------------------------------------------------------------------
extern "C" void kernel_launch(void* const* d_in, const int* in_sizes, int n_in,
                              void* d_out, int out_size)
{
    const float* x      = (const float*)d_in[0];
    const float* Wq     = (const float*)d_in[1];
    const float* Wv     = (const float*)d_in[2];
    const float* Wo     = (const float*)d_in[3];
    const float* Wg     = (const float*)d_in[4];
    const float* beta   = (const float*)d_in[5];
    const float* gamma  = (const float*)d_in[6];
    const float* lbeta  = (const float*)d_in[7];
    float* out          = (float*)d_out;

    __half *qh, *vh, *gh, *ret, *xh, *zh, *wh;
    cudaGetSymbolAddress((void**)&qh, g_qh);
    cudaGetSymbolAddress((void**)&vh, g_vh);
    cudaGetSymbolAddress((void**)&gh, g_gh);
    cudaGetSymbolAddress((void**)&ret, g_ret);
    cudaGetSymbolAddress((void**)&xh, g_xh);
    cudaGetSymbolAddress((void**)&zh, g_zh);
    cudaGetSymbolAddress((void**)&wh, g_wh);

    cudaFuncSetAttribute((const void*)gemm_mma<__half>, cudaFuncAttributeMaxDynamicSharedMemorySize, GEMM_SMEM);
    cudaFuncSetAttribute((const void*)gemm_mma<float>,  cudaFuncAttributeMaxDynamicSharedMemorySize, GEMM_SMEM);

    // Batched converts: x + 4 weights -> fp16 in one launch
    CvtArgs ca;
    ca.src[0] = x;  ca.dst[0] = xh;                      ca.n4[0] = Mtot*Dc/4;
    ca.src[1] = Wq; ca.dst[1] = wh + 0*(size_t)Dc*Dc;    ca.n4[1] = Dc*Dc/4;
    ca.src[2] = Wv; ca.dst[2] = wh + 1*(size_t)Dc*Dc;    ca.n4[2] = Dc*Dc/4;
    ca.src[3] = Wg; ca.dst[3] = wh + 2*(size_t)Dc*Dc;    ca.n4[3] = Dc*Dc/4;
    ca.src[4] = Wo; ca.dst[4] = wh + 3*(size_t)Dc*Dc;    ca.n4[4] = Dc*Dc/4;
    dim3 cgrid((Mtot*Dc/4 + 255)/256, 5);
    cvt5_kernel<<<cgrid, 256>>>(ca);

    // Fused q/v/g projection GEMMs (1-term fp16, fp16 outputs)
    GemmArgs<__half> a1;
    a1.Ah = xh;
    a1.Wh[0] = wh + 0*(size_t)Dc*Dc; a1.C[0] = qh;
    a1.Wh[1] = wh + 1*(size_t)Dc*Dc; a1.C[1] = vh;
    a1.Wh[2] = wh + 2*(size_t)Dc*Dc; a1.C[2] = gh;
    dim3 grid_qvg(Dc/NT, Mtot/MT, 3);   // (8, 128, 3)
    gemm_mma<__half><<<grid_qvg, 256, GEMM_SMEM>>>(a1);

    scan_pass1<<<Bc*Hc*NC, 64>>>(vh, beta);
    scan_pass2<<<(Bc*Hc*Dhc)/256, 256>>>(beta);
    scan_pass3<<<Bc*Hc*NC, 64>>>(vh, qh, ret, beta);

    ln_gate_kernel<<<Mtot, 256>>>(ret, gh, gamma, lbeta, zh);

    // Output GEMM (1-term fp16, fp32 output)
    GemmArgs<float> a2;
    a2.Ah = zh;
    a2.Wh[0] = wh + 3*(size_t)Dc*Dc; a2.C[0] = out;
    a2.Wh[1] = a2.Wh[0]; a2.C[1] = out;
    a2.Wh[2] = a2.Wh[0]; a2.C[2] = out;
    dim3 grid_o(Dc/NT, Mtot/MT, 1);     // (8, 128, 1)
    gemm_mma<float><<<grid_o, 256, GEMM_SMEM>>>(a2);
}

// round 14
// speedup vs baseline: 1.4386x; 1.4386x over previous
#include <cuda_runtime.h>
#include <cuda_fp16.h>
#include <math.h>
#include <stdint.h>

// Problem constants
#define Bc   4
#define Lc   4096
#define Dc   1024
#define Hc   16
#define Dhc  64
#define Mtot (Bc*Lc)        // 16384 rows
#define NC   32             // scan chunks per sequence
#define CHUNK (Lc/NC)       // 128

// GEMM tiling: 128x128 tile, 2 CTAs/SM
#define MT 128
#define NT 128
#define KT 32               // k per stage
#define NKC (Dc/KT)         // 32 k-chunks
#define TILE_B (MT*KT*2)            // 8192 bytes per operand tile
#define OFF_AH 0
#define OFF_WH (TILE_B)
#define OFF_WL (2*TILE_B)
#define STAGE_BYTES (3*TILE_B)      // 24576
#define NSTAGE 4
#define GEMM_SMEM (NSTAGE*STAGE_BYTES)     // 98304 -> 2 CTAs/SM

// Conflict-free swizzle: 16B-chunk c (0..3) xored with (row>>1)&3.
#define SWZ(row, ch) ((uint32_t)(row) * 64 + (uint32_t)((((ch) ^ (((row) >> 1) & 3)) & 3) * 16))

// ---------------------------------------------------------------------------
// Scratch (__device__ globals per allocation-free rule)
// ---------------------------------------------------------------------------
__device__ __half g_qh[Mtot*Dc];               // q (fp16)
__device__ __half g_vh[Mtot*Dc];               // v (fp16)
__device__ __half g_gh[Mtot*Dc];               // gate pre-activation (fp16)
__device__ __half g_ret[Mtot*Dc];              // ret = q*s (fp16)
__device__ float g_chunkS[Bc*Hc*NC*Dhc];
__device__ float g_carry [Bc*Hc*NC*Dhc];
__device__ __half g_xh[Mtot*Dc];               // x in fp16
__device__ __half g_zh[Mtot*Dc];               // z in fp16
__device__ __half g_wh[4*Dc*Dc];               // Wq,Wv,Wg,Wo hi
__device__ __half g_wl[4*Dc*Dc];               // lo (unused by 1-term GEMMs)

// ---------------------------------------------------------------------------
// PTX helpers
// ---------------------------------------------------------------------------
__device__ __forceinline__ uint32_t smem_to_u32(const void* p) {
    uint32_t a;
    asm("{ .reg .u64 t; cvta.to.shared.u64 t, %1; cvt.u32.u64 %0, t; }" : "=r"(a) : "l"(p));
    return a;
}

#define CP16(dst, src) \
    asm volatile("cp.async.cg.shared.global [%0], [%1], 16;" :: "r"(dst), "l"(src) : "memory")

__device__ __forceinline__ void ldsm_x4(uint32_t (&r)[4], uint32_t addr) {
    asm volatile("ldmatrix.sync.aligned.m8n8.x4.shared.b16 {%0,%1,%2,%3}, [%4];"
        : "=r"(r[0]), "=r"(r[1]), "=r"(r[2]), "=r"(r[3]) : "r"(addr));
}

__device__ __forceinline__ void mma16816(float (&c)[4], const uint32_t (&a)[4],
                                         uint32_t b0, uint32_t b1) {
    asm volatile("mma.sync.aligned.m16n8k16.row.col.f32.f16.f16.f32 "
        "{%0,%1,%2,%3}, {%4,%5,%6,%7}, {%8,%9}, {%0,%1,%2,%3};"
        : "+f"(c[0]), "+f"(c[1]), "+f"(c[2]), "+f"(c[3])
        : "r"(a[0]), "r"(a[1]), "r"(a[2]), "r"(a[3]), "r"(b0), "r"(b1));
}

// ---------------------------------------------------------------------------
// Weight split fp32 -> (hi fp16, lo fp16); batched over 4 weights
// ---------------------------------------------------------------------------
struct SplitWArgs {
    const float* src[4];
    __half* hi[4];
    __half* lo[4];
};

__global__ __launch_bounds__(256)
void split_w_kernel(const SplitWArgs args)
{
    const int z = blockIdx.y;
    const float* s = args.src[z];
    __half* hi = args.hi[z];
    __half* lo = args.lo[z];

    int i = blockIdx.x * 256 + threadIdx.x;
    if (i >= Dc*Dc/4) return;
    float4 f = ((const float4*)s)[i];
    __half h0 = __float2half_rn(f.x), h1 = __float2half_rn(f.y);
    __half h2 = __float2half_rn(f.z), h3 = __float2half_rn(f.w);
    __half l0 = __float2half_rn(f.x - __half2float(h0));
    __half l1 = __float2half_rn(f.y - __half2float(h1));
    __half l2 = __float2half_rn(f.z - __half2float(h2));
    __half l3 = __float2half_rn(f.w - __half2float(h3));
    __half2 hp0(h0, h1), hp1(h2, h3), lp0(l0, l1), lp1(l2, l3);
    uint2 hv, lv;
    hv.x = *(uint32_t*)&hp0; hv.y = *(uint32_t*)&hp1;
    lv.x = *(uint32_t*)&lp0; lv.y = *(uint32_t*)&lp1;
    ((uint2*)hi)[i] = hv;
    ((uint2*)lo)[i] = lv;
}

// Activation convert fp32 -> fp16 (hi only)
__global__ __launch_bounds__(256)
void cvt_kernel(const float* __restrict__ s, __half* __restrict__ hi, int n4)
{
    int i = blockIdx.x * 256 + threadIdx.x;
    if (i >= n4) return;
    float4 f = ((const float4*)s)[i];
    __half2 hp0 = __floats2half2_rn(f.x, f.y);
    __half2 hp1 = __floats2half2_rn(f.z, f.w);
    uint2 hv;
    hv.x = *(uint32_t*)&hp0; hv.y = *(uint32_t*)&hp1;
    ((uint2*)hi)[i] = hv;
}

// ---------------------------------------------------------------------------
// mma.sync GEMM: C[m,n] = sum_k A[m,k]*W[n,k].
// TERMS=1: pure fp16 (A x Wh). TERMS=2: fp16 2-term (A x Wh + A x Wl).
// 128x128 CTA tile, 8 warps (32x64 each), K-chunk 32, 4-stage, 2 CTAs/SM.
// ---------------------------------------------------------------------------
template <typename OutT>
struct GemmArgs {
    const __half* Ah;
    const __half* Wh[3];
    const __half* Wl[3];
    OutT* C[3];
};

template <typename OutT, int TERMS>
__global__ __launch_bounds__(256, 2)
void gemm_mma(const GemmArgs<OutT> args)
{
    extern __shared__ char smem[];
    const uint32_t sbase = smem_to_u32(smem);
    const int tid  = threadIdx.x;
    const int lane = tid & 31;
    const int wid  = tid >> 5;
    const int wm   = wid & 3;
    const int wn   = wid >> 2;
    const int bn   = blockIdx.x * NT;
    const int bm   = blockIdx.y * MT;
    const int z    = blockIdx.z;

    const __half* __restrict__ Ah = args.Ah;
    const __half* __restrict__ Wh = args.Wh[z];
    const __half* __restrict__ Wl = args.Wl[z];
    OutT* __restrict__ C = args.C[z];

    const int row0 = tid >> 2;
    const int ch0  = tid & 3;

    auto load_stage = [&](int st, int kc) {
        const uint32_t sb = sbase + (uint32_t)st * STAGE_BYTES;
        const int k0 = kc * KT;
        #pragma unroll
        for (int rep = 0; rep < 2; rep++) {
            int row = row0 + rep * 64;
            uint32_t sw = SWZ(row, ch0);
            const __half* pa = Ah + (size_t)(bm + row) * Dc + k0 + ch0 * 8;
            const __half* pw = Wh + (size_t)(bn + row) * Dc + k0 + ch0 * 8;
            CP16(sb + OFF_AH + sw, pa);
            CP16(sb + OFF_WH + sw, pw);
            if (TERMS == 2) {
                const __half* pq = Wl + (size_t)(bn + row) * Dc + k0 + ch0 * 8;
                CP16(sb + OFF_WL + sw, pq);
            }
        }
        asm volatile("cp.async.commit_group;" ::: "memory");
    };

    float c[2][8][4];
    #pragma unroll
    for (int i = 0; i < 2; i++)
        #pragma unroll
        for (int j = 0; j < 8; j++)
            #pragma unroll
            for (int k = 0; k < 4; k++) c[i][j][k] = 0.0f;

    load_stage(0, 0);
    load_stage(1, 1);
    load_stage(2, 2);

    const int a_r  = lane & 15;
    const int a_kc = lane >> 4;
    const int b_r  = ((lane >> 4) << 3) + (lane & 7);
    const int b_kc = (lane >> 3) & 1;

    for (int kc = 0; kc < NKC; kc++) {
        const int st = kc % NSTAGE;
        asm volatile("cp.async.wait_group 2;" ::: "memory");
        __syncthreads();

        if (kc + 3 < NKC) load_stage((kc + 3) % NSTAGE, kc + 3);
        else asm volatile("cp.async.commit_group;" ::: "memory");

        const uint32_t sb = sbase + (uint32_t)st * STAGE_BYTES;

        #pragma unroll
        for (int ks = 0; ks < 2; ks++) {
            uint32_t ah[2][4];
            #pragma unroll
            for (int mi = 0; mi < 2; mi++) {
                int row = wm * 32 + mi * 16 + a_r;
                int kk  = ks * 2 + a_kc;
                ldsm_x4(ah[mi], sb + OFF_AH + SWZ(row, kk));
            }
            #pragma unroll
            for (int half = 0; half < 2; half++) {
                uint32_t bh[2][4], bl[2][4];
                #pragma unroll
                for (int p = 0; p < 2; p++) {
                    int pr  = half * 2 + p;
                    int row = wn * 64 + pr * 16 + b_r;
                    int kk  = ks * 2 + b_kc;
                    uint32_t sw = SWZ(row, kk);
                    ldsm_x4(bh[p], sb + OFF_WH + sw);
                    if (TERMS == 2) ldsm_x4(bl[p], sb + OFF_WL + sw);
                }
                #pragma unroll
                for (int mi = 0; mi < 2; mi++)
                    #pragma unroll
                    for (int p = 0; p < 2; p++) {
                        int ni = (half * 2 + p) * 2;
                        mma16816(c[mi][ni+0], ah[mi], bh[p][0], bh[p][1]);
                        mma16816(c[mi][ni+1], ah[mi], bh[p][2], bh[p][3]);
                    }
                if (TERMS == 2) {
                    #pragma unroll
                    for (int mi = 0; mi < 2; mi++)
                        #pragma unroll
                        for (int p = 0; p < 2; p++) {
                            int ni = (half * 2 + p) * 2;
                            mma16816(c[mi][ni+0], ah[mi], bl[p][0], bl[p][1]);
                            mma16816(c[mi][ni+1], ah[mi], bl[p][2], bl[p][3]);
                        }
                }
            }
        }
    }

    const int er = lane >> 2;
    const int ec = (lane & 3) * 2;
    #pragma unroll
    for (int mi = 0; mi < 2; mi++) {
        #pragma unroll
        for (int ni = 0; ni < 8; ni++) {
            size_t r0g = (size_t)(bm + wm * 32 + mi * 16 + er);
            size_t cg  = (size_t)(bn + wn * 64 + ni * 8 + ec);
            if constexpr (sizeof(OutT) == 4) {
                float2* p0 = (float2*)((float*)C + r0g * Dc + cg);
                float2* p1 = (float2*)((float*)C + (r0g + 8) * Dc + cg);
                *p0 = make_float2(c[mi][ni][0], c[mi][ni][1]);
                *p1 = make_float2(c[mi][ni][2], c[mi][ni][3]);
            } else {
                __half2 h0 = __floats2half2_rn(c[mi][ni][0], c[mi][ni][1]);
                __half2 h1 = __floats2half2_rn(c[mi][ni][2], c[mi][ni][3]);
                *(__half2*)((__half*)C + r0g * Dc + cg)       = h0;
                *(__half2*)((__half*)C + (r0g + 8) * Dc + cg) = h1;
            }
        }
    }
}

// ---------------------------------------------------------------------------
// Retention scan (fp16 storage, fp32 accumulation)
// ---------------------------------------------------------------------------
__device__ __forceinline__ float lam_of(const float* beta, int h)
{
    float lam = 1.0f - exp2f(-beta[h]);
    lam = fmaxf(lam, 1.17549435e-38f);
    lam = fminf(lam, 1.0f);
    return lam;
}

__global__ __launch_bounds__(64)
void scan_pass1(const __half* __restrict__ v, const float* __restrict__ beta)
{
    int blk = blockIdx.x;
    int cc  = blk % NC;
    int bh  = blk / NC;
    int h   = bh % Hc;
    int b   = bh / Hc;
    int dh  = threadIdx.x;

    float lam = lam_of(beta, h);
    size_t off = ((size_t)(b*Lc + cc*CHUNK)) * Dc + h*Dhc + dh;

    float s = 0.0f;
    #pragma unroll
    for (int t0 = 0; t0 < CHUNK; t0 += 16) {
        __half vals[16];
        #pragma unroll
        for (int j = 0; j < 16; j++)
            vals[j] = v[off + (size_t)j * Dc];
        #pragma unroll
        for (int j = 0; j < 16; j++)
            s = fmaf(lam, s, __half2float(vals[j]));
        off += (size_t)16 * Dc;
    }
    g_chunkS[(size_t)(bh*NC + cc)*Dhc + dh] = s;
}

__global__ __launch_bounds__(256)
void scan_pass2(const float* __restrict__ beta)
{
    int idx = blockIdx.x * blockDim.x + threadIdx.x;  // 0..4095
    int dh  = idx & 63;
    int bh  = idx >> 6;
    int h   = bh & (Hc - 1);

    float lam = lam_of(beta, h);
    float lamP = lam;
    #pragma unroll
    for (int i = 0; i < 7; i++) lamP = lamP * lamP;   // lam^128

    float cs[NC];
    #pragma unroll
    for (int cc = 0; cc < NC; cc++)
        cs[cc] = g_chunkS[(size_t)(bh*NC + cc)*Dhc + dh];

    float carry = 0.0f;
    #pragma unroll
    for (int cc = 0; cc < NC; cc++) {
        g_carry[(size_t)(bh*NC + cc)*Dhc + dh] = carry;
        carry = fmaf(lamP, carry, cs[cc]);
    }
}

__global__ __launch_bounds__(64)
void scan_pass3(const __half* __restrict__ v, const __half* __restrict__ q,
                __half* __restrict__ ret, const float* __restrict__ beta)
{
    int blk = blockIdx.x;
    int cc  = blk % NC;
    int bh  = blk / NC;
    int h   = bh % Hc;
    int b   = bh / Hc;
    int dh  = threadIdx.x;

    float lam = lam_of(beta, h);
    size_t off = ((size_t)(b*Lc + cc*CHUNK)) * Dc + h*Dhc + dh;

    float s = g_carry[(size_t)(bh*NC + cc)*Dhc + dh];
    #pragma unroll
    for (int t0 = 0; t0 < CHUNK; t0 += 8) {
        __half vv[8], qq[8];
        #pragma unroll
        for (int j = 0; j < 8; j++) {
            vv[j] = v[off + (size_t)j * Dc];
            qq[j] = q[off + (size_t)j * Dc];
        }
        #pragma unroll
        for (int j = 0; j < 8; j++) {
            s = fmaf(lam, s, __half2float(vv[j]));
            ret[off + (size_t)j * Dc] = __float2half_rn(__half2float(qq[j]) * s);
        }
        off += (size_t)8 * Dc;
    }
}

// ---------------------------------------------------------------------------
// Fused LayerNorm(ret) * SiLU(gate) -> z fp16 (fp16 in, fp32 reduce)
// ---------------------------------------------------------------------------
__global__ __launch_bounds__(256)
void ln_gate_kernel(const __half* __restrict__ ret, const __half* __restrict__ gate,
                    const float* __restrict__ gamma, const float* __restrict__ lbeta,
                    __half* __restrict__ zh)
{
    const size_t row = blockIdx.x;
    const int tid = threadIdx.x;

    uint2 rv = ((const uint2*)(ret  + row*Dc))[tid];
    uint2 gv = ((const uint2*)(gate + row*Dc))[tid];
    __half2 r01 = *(__half2*)&rv.x, r23 = *(__half2*)&rv.y;
    __half2 g01 = *(__half2*)&gv.x, g23 = *(__half2*)&gv.y;
    float r0 = __half2float(r01.x), r1 = __half2float(r01.y);
    float r2 = __half2float(r23.x), r3 = __half2float(r23.y);
    float g0 = __half2float(g01.x), g1 = __half2float(g01.y);
    float g2 = __half2float(g23.x), g3 = __half2float(g23.y);

    float s  = r0 + r1 + r2 + r3;
    float ss = r0*r0 + r1*r1 + r2*r2 + r3*r3;

    #pragma unroll
    for (int o = 16; o > 0; o >>= 1) {
        s  += __shfl_xor_sync(0xffffffffu, s,  o);
        ss += __shfl_xor_sync(0xffffffffu, ss, o);
    }
    __shared__ float shs[8], shq[8];
    if ((tid & 31) == 0) { shs[tid>>5] = s; shq[tid>>5] = ss; }
    __syncthreads();

    float tot = 0.0f, totq = 0.0f;
    #pragma unroll
    for (int i = 0; i < 8; i++) { tot += shs[i]; totq += shq[i]; }

    const float inv = 1.0f / (float)Dc;
    float mu   = tot * inv;
    float var  = totq * inv - mu * mu;
    float rstd = rsqrtf(var + 1e-5f);

    const float4 gm = ((const float4*)gamma)[tid];
    const float4 bt = ((const float4*)lbeta)[tid];

    float o0 = ((r0 - mu)*rstd*gm.x + bt.x) * (g0 / (1.0f + expf(-g0)));
    float o1 = ((r1 - mu)*rstd*gm.y + bt.y) * (g1 / (1.0f + expf(-g1)));
    float o2 = ((r2 - mu)*rstd*gm.z + bt.z) * (g2 / (1.0f + expf(-g2)));
    float o3 = ((r3 - mu)*rstd*gm.w + bt.w) * (g3 / (1.0f + expf(-g3)));

    __half2 hp0 = __floats2half2_rn(o0, o1);
    __half2 hp1 = __floats2half2_rn(o2, o3);
    uint2 hv;
    hv.x = *(uint32_t*)&hp0; hv.y = *(uint32_t*)&hp1;
    ((uint2*)(zh + row*Dc))[tid] = hv;
}

// ---------------------------------------------------------------------------
// Launch
// ---------------------------------------------------------------------------
extern "C" void kernel_launch(void* const* d_in, const int* in_sizes, int n_in,
                              void* d_out, int out_size)
{
    const float* x      = (const float*)d_in[0];
    const float* Wq     = (const float*)d_in[1];
    const float* Wv     = (const float*)d_in[2];
    const float* Wo     = (const float*)d_in[3];
    const float* Wg     = (const float*)d_in[4];
    const float* beta   = (const float*)d_in[5];
    const float* gamma  = (const float*)d_in[6];
    const float* lbeta  = (const float*)d_in[7];
    float* out          = (float*)d_out;

    __half *qh, *vh, *gh, *ret, *xh, *zh, *wh, *wl;
    cudaGetSymbolAddress((void**)&qh, g_qh);
    cudaGetSymbolAddress((void**)&vh, g_vh);
    cudaGetSymbolAddress((void**)&gh, g_gh);
    cudaGetSymbolAddress((void**)&ret, g_ret);
    cudaGetSymbolAddress((void**)&xh, g_xh);
    cudaGetSymbolAddress((void**)&zh, g_zh);
    cudaGetSymbolAddress((void**)&wh, g_wh);
    cudaGetSymbolAddress((void**)&wl, g_wl);

    cudaFuncSetAttribute((const void*)gemm_mma<__half,1>, cudaFuncAttributeMaxDynamicSharedMemorySize, GEMM_SMEM);
    cudaFuncSetAttribute((const void*)gemm_mma<float,1>,  cudaFuncAttributeMaxDynamicSharedMemorySize, GEMM_SMEM);

    // Weight splits (4 weights, batched) — same as the verified 533.7us config
    SplitWArgs sw;
    sw.src[0] = Wq; sw.hi[0] = wh + 0*(size_t)Dc*Dc; sw.lo[0] = wl + 0*(size_t)Dc*Dc;
    sw.src[1] = Wv; sw.hi[1] = wh + 1*(size_t)Dc*Dc; sw.lo[1] = wl + 1*(size_t)Dc*Dc;
    sw.src[2] = Wg; sw.hi[2] = wh + 2*(size_t)Dc*Dc; sw.lo[2] = wl + 2*(size_t)Dc*Dc;
    sw.src[3] = Wo; sw.hi[3] = wh + 3*(size_t)Dc*Dc; sw.lo[3] = wl + 3*(size_t)Dc*Dc;
    dim3 wgrid((Dc*Dc/4 + 255)/256, 4);
    split_w_kernel<<<wgrid, 256>>>(sw);

    // x -> fp16
    cvt_kernel<<<(Mtot*Dc/4 + 255)/256, 256>>>(x, xh, Mtot*Dc/4);

    // Fused q/v/g projection GEMMs (1-term fp16, fp16 outputs)
    GemmArgs<__half> a1;
    a1.Ah = xh;
    a1.Wh[0] = wh + 0*(size_t)Dc*Dc; a1.Wl[0] = wl + 0*(size_t)Dc*Dc; a1.C[0] = qh;
    a1.Wh[1] = wh + 1*(size_t)Dc*Dc; a1.Wl[1] = wl + 1*(size_t)Dc*Dc; a1.C[1] = vh;
    a1.Wh[2] = wh + 2*(size_t)Dc*Dc; a1.Wl[2] = wl + 2*(size_t)Dc*Dc; a1.C[2] = gh;
    dim3 grid_qvg(Dc/NT, Mtot/MT, 3);   // (8, 128, 3)
    gemm_mma<__half,1><<<grid_qvg, 256, GEMM_SMEM>>>(a1);

    scan_pass1<<<Bc*Hc*NC, 64>>>(vh, beta);
    scan_pass2<<<(Bc*Hc*Dhc)/256, 256>>>(beta);
    scan_pass3<<<Bc*Hc*NC, 64>>>(vh, qh, ret, beta);

    ln_gate_kernel<<<Mtot, 256>>>(ret, gh, gamma, lbeta, zh);

    // Output GEMM — ONLY change vs the 533.7us config: TERMS 2 -> 1
    GemmArgs<float> a2;
    a2.Ah = zh;
    a2.Wh[0] = wh + 3*(size_t)Dc*Dc; a2.Wl[0] = wl + 3*(size_t)Dc*Dc; a2.C[0] = out;
    a2.Wh[1] = a2.Wh[0]; a2.Wl[1] = a2.Wl[0]; a2.C[1] = out;
    a2.Wh[2] = a2.Wh[0]; a2.Wl[2] = a2.Wl[0]; a2.C[2] = out;
    dim3 grid_o(Dc/NT, Mtot/MT, 1);     // (8, 128, 1)
    gemm_mma<float,1><<<grid_o, 256, GEMM_SMEM>>>(a2);
}

// round 15
// speedup vs baseline: 1.4924x; 1.0374x over previous
#include <cuda_runtime.h>
#include <cuda_fp16.h>
#include <math.h>
#include <stdint.h>

// Problem constants
#define Bc   4
#define Lc   4096
#define Dc   1024
#define Hc   16
#define Dhc  64
#define Mtot (Bc*Lc)        // 16384 rows
#define NC   32             // scan chunks per sequence
#define CHUNK (Lc/NC)       // 128

// GEMM tiling: 128x128 tile, KT=64 k-chunk (canonical SW128), 2 CTAs/SM
#define MT 128
#define NT 128
#define KT 64               // k per stage (128 bytes/row = SW128 atom)
#define NKC (Dc/KT)         // 16 k-chunks
#define TILE_B (MT*KT*2)            // 16384 bytes per operand tile
#define OFF_AH 0
#define OFF_WH (TILE_B)
#define STAGE_BYTES (2*TILE_B)      // 32768
#define NSTAGE 3
#define GEMM_SMEM (NSTAGE*STAGE_BYTES)     // 98304 -> 2 CTAs/SM

// Canonical SW128 swizzle for 128-byte rows (verified pattern)
#define SWZ128(off) ((uint32_t)(off) ^ (((uint32_t)(off) >> 3) & 0x70u))

// ---------------------------------------------------------------------------
// Scratch (__device__ globals per allocation-free rule)
// ---------------------------------------------------------------------------
__device__ __half g_qh[Mtot*Dc];               // q (fp16)
__device__ __half g_vh[Mtot*Dc];               // v (fp16)
__device__ __half g_gh[Mtot*Dc];               // gate pre-activation (fp16)
__device__ __half g_ret[Mtot*Dc];              // ret = q*s (fp16)
__device__ float g_chunkS[Bc*Hc*NC*Dhc];
__device__ float g_carry [Bc*Hc*NC*Dhc];
__device__ __half g_xh[Mtot*Dc];               // x in fp16
__device__ __half g_zh[Mtot*Dc];               // z in fp16
__device__ __half g_wh[4*Dc*Dc];               // Wq,Wv,Wg,Wo in fp16

// ---------------------------------------------------------------------------
// PTX helpers
// ---------------------------------------------------------------------------
__device__ __forceinline__ uint32_t smem_to_u32(const void* p) {
    uint32_t a;
    asm("{ .reg .u64 t; cvta.to.shared.u64 t, %1; cvt.u32.u64 %0, t; }" : "=r"(a) : "l"(p));
    return a;
}

#define CP16(dst, src) \
    asm volatile("cp.async.cg.shared.global [%0], [%1], 16;" :: "r"(dst), "l"(src) : "memory")

__device__ __forceinline__ void ldsm_x4(uint32_t (&r)[4], uint32_t addr) {
    asm volatile("ldmatrix.sync.aligned.m8n8.x4.shared.b16 {%0,%1,%2,%3}, [%4];"
        : "=r"(r[0]), "=r"(r[1]), "=r"(r[2]), "=r"(r[3]) : "r"(addr));
}

__device__ __forceinline__ void mma16816(float (&c)[4], const uint32_t (&a)[4],
                                         uint32_t b0, uint32_t b1) {
    asm volatile("mma.sync.aligned.m16n8k16.row.col.f32.f16.f16.f32 "
        "{%0,%1,%2,%3}, {%4,%5,%6,%7}, {%8,%9}, {%0,%1,%2,%3};"
        : "+f"(c[0]), "+f"(c[1]), "+f"(c[2]), "+f"(c[3])
        : "r"(a[0]), "r"(a[1]), "r"(a[2]), "r"(a[3]), "r"(b0), "r"(b1));
}

// ---------------------------------------------------------------------------
// Weight convert fp32 -> fp16 (hi only; lo halves no longer used anywhere).
// Same 4-way batched launch shape as the verified split_w config.
// ---------------------------------------------------------------------------
struct CvtWArgs {
    const float* src[4];
    __half* dst[4];
};

__global__ __launch_bounds__(256)
void cvt_w_kernel(const CvtWArgs args)
{
    const int z = blockIdx.y;
    const float* s = args.src[z];
    __half* d = args.dst[z];

    int i = blockIdx.x * 256 + threadIdx.x;
    if (i >= Dc*Dc/4) return;
    float4 f = ((const float4*)s)[i];
    __half2 hp0 = __floats2half2_rn(f.x, f.y);
    __half2 hp1 = __floats2half2_rn(f.z, f.w);
    uint2 hv;
    hv.x = *(uint32_t*)&hp0; hv.y = *(uint32_t*)&hp1;
    ((uint2*)d)[i] = hv;
}

// Activation convert fp32 -> fp16
__global__ __launch_bounds__(256)
void cvt_kernel(const float* __restrict__ s, __half* __restrict__ hi, int n4)
{
    int i = blockIdx.x * 256 + threadIdx.x;
    if (i >= n4) return;
    float4 f = ((const float4*)s)[i];
    __half2 hp0 = __floats2half2_rn(f.x, f.y);
    __half2 hp1 = __floats2half2_rn(f.z, f.w);
    uint2 hv;
    hv.x = *(uint32_t*)&hp0; hv.y = *(uint32_t*)&hp1;
    ((uint2*)hi)[i] = hv;
}

// ---------------------------------------------------------------------------
// mma.sync GEMM: C[m,n] = sum_k A[m,k]*W[n,k], pure fp16, fp32 accum.
// 128x128 CTA tile, 8 warps (32x64 each), KT=64 (canonical SW128),
// 3-stage cp.async, 2 CTAs/SM.
// ---------------------------------------------------------------------------
template <typename OutT>
struct GemmArgs {
    const __half* Ah;
    const __half* Wh[3];
    OutT* C[3];
};

template <typename OutT>
__global__ __launch_bounds__(256, 2)
void gemm_mma(const GemmArgs<OutT> args)
{
    extern __shared__ char smem[];
    const uint32_t sbase = smem_to_u32(smem);
    const int tid  = threadIdx.x;
    const int lane = tid & 31;
    const int wid  = tid >> 5;
    const int wm   = wid & 3;
    const int wn   = wid >> 2;
    const int bn   = blockIdx.x * NT;
    const int bm   = blockIdx.y * MT;
    const int z    = blockIdx.z;

    const __half* __restrict__ Ah = args.Ah;
    const __half* __restrict__ Wh = args.Wh[z];
    OutT* __restrict__ C = args.C[z];

    auto load_stage = [&](int st, int kc) {
        const uint32_t sb = sbase + (uint32_t)st * STAGE_BYTES;
        const int k0 = kc * KT;
        #pragma unroll
        for (int it = 0; it < 4; it++) {
            int idx = tid + it * 256;       // 0..1023
            int row = idx >> 3;             // 0..127
            int ch  = idx & 7;              // 0..7 (16B chunks in 128B row)
            uint32_t sw = SWZ128((uint32_t)row * 128 + (uint32_t)ch * 16);
            const __half* pa = Ah + (size_t)(bm + row) * Dc + k0 + ch * 8;
            const __half* pw = Wh + (size_t)(bn + row) * Dc + k0 + ch * 8;
            CP16(sb + OFF_AH + sw, pa);
            CP16(sb + OFF_WH + sw, pw);
        }
        asm volatile("cp.async.commit_group;" ::: "memory");
    };

    float c[2][8][4];
    #pragma unroll
    for (int i = 0; i < 2; i++)
        #pragma unroll
        for (int j = 0; j < 8; j++)
            #pragma unroll
            for (int k = 0; k < 4; k++) c[i][j][k] = 0.0f;

    load_stage(0, 0);
    load_stage(1, 1);

    const int a_r  = lane & 15;            // A m16k16 row within tile
    const int a_kc = lane >> 4;            // 16B chunk select (0/1)
    const int b_r  = ((lane >> 4) << 3) + (lane & 7);  // B n16k16
    const int b_kc = (lane >> 3) & 1;

    for (int kc = 0; kc < NKC; kc++) {
        const int st = kc % NSTAGE;
        asm volatile("cp.async.wait_group 1;" ::: "memory");
        __syncthreads();

        if (kc + 2 < NKC) load_stage((kc + 2) % NSTAGE, kc + 2);
        else asm volatile("cp.async.commit_group;" ::: "memory");

        const uint32_t sb = sbase + (uint32_t)st * STAGE_BYTES;

        #pragma unroll
        for (int ks = 0; ks < 4; ks++) {   // 4 k16 steps within KT=64
            uint32_t ah[2][4];
            #pragma unroll
            for (int mi = 0; mi < 2; mi++) {
                int row = wm * 32 + mi * 16 + a_r;
                uint32_t off = (uint32_t)row * 128 + (uint32_t)(ks * 2 + a_kc) * 16;
                ldsm_x4(ah[mi], sb + OFF_AH + SWZ128(off));
            }
            #pragma unroll
            for (int half = 0; half < 2; half++) {
                uint32_t bh[2][4];
                #pragma unroll
                for (int p = 0; p < 2; p++) {
                    int pr  = half * 2 + p;
                    int row = wn * 64 + pr * 16 + b_r;
                    uint32_t off = (uint32_t)row * 128 + (uint32_t)(ks * 2 + b_kc) * 16;
                    ldsm_x4(bh[p], sb + OFF_WH + SWZ128(off));
                }
                #pragma unroll
                for (int mi = 0; mi < 2; mi++)
                    #pragma unroll
                    for (int p = 0; p < 2; p++) {
                        int ni = (half * 2 + p) * 2;
                        mma16816(c[mi][ni+0], ah[mi], bh[p][0], bh[p][1]);
                        mma16816(c[mi][ni+1], ah[mi], bh[p][2], bh[p][3]);
                    }
            }
        }
    }

    const int er = lane >> 2;
    const int ec = (lane & 3) * 2;
    #pragma unroll
    for (int mi = 0; mi < 2; mi++) {
        #pragma unroll
        for (int ni = 0; ni < 8; ni++) {
            size_t r0g = (size_t)(bm + wm * 32 + mi * 16 + er);
            size_t cg  = (size_t)(bn + wn * 64 + ni * 8 + ec);
            if constexpr (sizeof(OutT) == 4) {
                float2* p0 = (float2*)((float*)C + r0g * Dc + cg);
                float2* p1 = (float2*)((float*)C + (r0g + 8) * Dc + cg);
                *p0 = make_float2(c[mi][ni][0], c[mi][ni][1]);
                *p1 = make_float2(c[mi][ni][2], c[mi][ni][3]);
            } else {
                __half2 h0 = __floats2half2_rn(c[mi][ni][0], c[mi][ni][1]);
                __half2 h1 = __floats2half2_rn(c[mi][ni][2], c[mi][ni][3]);
                *(__half2*)((__half*)C + r0g * Dc + cg)       = h0;
                *(__half2*)((__half*)C + (r0g + 8) * Dc + cg) = h1;
            }
        }
    }
}

// ---------------------------------------------------------------------------
// Retention scan (fp16 storage, fp32 accumulation)
// ---------------------------------------------------------------------------
__device__ __forceinline__ float lam_of(const float* beta, int h)
{
    float lam = 1.0f - exp2f(-beta[h]);
    lam = fmaxf(lam, 1.17549435e-38f);
    lam = fminf(lam, 1.0f);
    return lam;
}

__global__ __launch_bounds__(64)
void scan_pass1(const __half* __restrict__ v, const float* __restrict__ beta)
{
    int blk = blockIdx.x;
    int cc  = blk % NC;
    int bh  = blk / NC;
    int h   = bh % Hc;
    int b   = bh / Hc;
    int dh  = threadIdx.x;

    float lam = lam_of(beta, h);
    size_t off = ((size_t)(b*Lc + cc*CHUNK)) * Dc + h*Dhc + dh;

    float s = 0.0f;
    #pragma unroll
    for (int t0 = 0; t0 < CHUNK; t0 += 16) {
        __half vals[16];
        #pragma unroll
        for (int j = 0; j < 16; j++)
            vals[j] = v[off + (size_t)j * Dc];
        #pragma unroll
        for (int j = 0; j < 16; j++)
            s = fmaf(lam, s, __half2float(vals[j]));
        off += (size_t)16 * Dc;
    }
    g_chunkS[(size_t)(bh*NC + cc)*Dhc + dh] = s;
}

__global__ __launch_bounds__(256)
void scan_pass2(const float* __restrict__ beta)
{
    int idx = blockIdx.x * blockDim.x + threadIdx.x;  // 0..4095
    int dh  = idx & 63;
    int bh  = idx >> 6;
    int h   = bh & (Hc - 1);

    float lam = lam_of(beta, h);
    float lamP = lam;
    #pragma unroll
    for (int i = 0; i < 7; i++) lamP = lamP * lamP;   // lam^128

    float cs[NC];
    #pragma unroll
    for (int cc = 0; cc < NC; cc++)
        cs[cc] = g_chunkS[(size_t)(bh*NC + cc)*Dhc + dh];

    float carry = 0.0f;
    #pragma unroll
    for (int cc = 0; cc < NC; cc++) {
        g_carry[(size_t)(bh*NC + cc)*Dhc + dh] = carry;
        carry = fmaf(lamP, carry, cs[cc]);
    }
}

__global__ __launch_bounds__(64)
void scan_pass3(const __half* __restrict__ v, const __half* __restrict__ q,
                __half* __restrict__ ret, const float* __restrict__ beta)
{
    int blk = blockIdx.x;
    int cc  = blk % NC;
    int bh  = blk / NC;
    int h   = bh % Hc;
    int b   = bh / Hc;
    int dh  = threadIdx.x;

    float lam = lam_of(beta, h);
    size_t off = ((size_t)(b*Lc + cc*CHUNK)) * Dc + h*Dhc + dh;

    float s = g_carry[(size_t)(bh*NC + cc)*Dhc + dh];
    #pragma unroll
    for (int t0 = 0; t0 < CHUNK; t0 += 16) {
        __half vv[16], qq[16];
        #pragma unroll
        for (int j = 0; j < 16; j++) {
            vv[j] = v[off + (size_t)j * Dc];
            qq[j] = q[off + (size_t)j * Dc];
        }
        #pragma unroll
        for (int j = 0; j < 16; j++) {
            s = fmaf(lam, s, __half2float(vv[j]));
            ret[off + (size_t)j * Dc] = __float2half_rn(__half2float(qq[j]) * s);
        }
        off += (size_t)16 * Dc;
    }
}

// ---------------------------------------------------------------------------
// Fused LayerNorm(ret) * SiLU(gate) -> z fp16 (fp16 in, fp32 reduce)
// ---------------------------------------------------------------------------
__global__ __launch_bounds__(256)
void ln_gate_kernel(const __half* __restrict__ ret, const __half* __restrict__ gate,
                    const float* __restrict__ gamma, const float* __restrict__ lbeta,
                    __half* __restrict__ zh)
{
    const size_t row = blockIdx.x;
    const int tid = threadIdx.x;

    uint2 rv = ((const uint2*)(ret  + row*Dc))[tid];
    uint2 gv = ((const uint2*)(gate + row*Dc))[tid];
    __half2 r01 = *(__half2*)&rv.x, r23 = *(__half2*)&rv.y;
    __half2 g01 = *(__half2*)&gv.x, g23 = *(__half2*)&gv.y;
    float r0 = __half2float(r01.x), r1 = __half2float(r01.y);
    float r2 = __half2float(r23.x), r3 = __half2float(r23.y);
    float g0 = __half2float(g01.x), g1 = __half2float(g01.y);
    float g2 = __half2float(g23.x), g3 = __half2float(g23.y);

    float s  = r0 + r1 + r2 + r3;
    float ss = r0*r0 + r1*r1 + r2*r2 + r3*r3;

    #pragma unroll
    for (int o = 16; o > 0; o >>= 1) {
        s  += __shfl_xor_sync(0xffffffffu, s,  o);
        ss += __shfl_xor_sync(0xffffffffu, ss, o);
    }
    __shared__ float shs[8], shq[8];
    if ((tid & 31) == 0) { shs[tid>>5] = s; shq[tid>>5] = ss; }
    __syncthreads();

    float tot = 0.0f, totq = 0.0f;
    #pragma unroll
    for (int i = 0; i < 8; i++) { tot += shs[i]; totq += shq[i]; }

    const float inv = 1.0f / (float)Dc;
    float mu   = tot * inv;
    float var  = totq * inv - mu * mu;
    float rstd = rsqrtf(var + 1e-5f);

    const float4 gm = ((const float4*)gamma)[tid];
    const float4 bt = ((const float4*)lbeta)[tid];

    float o0 = ((r0 - mu)*rstd*gm.x + bt.x) * (g0 / (1.0f + expf(-g0)));
    float o1 = ((r1 - mu)*rstd*gm.y + bt.y) * (g1 / (1.0f + expf(-g1)));
    float o2 = ((r2 - mu)*rstd*gm.z + bt.z) * (g2 / (1.0f + expf(-g2)));
    float o3 = ((r3 - mu)*rstd*gm.w + bt.w) * (g3 / (1.0f + expf(-g3)));

    __half2 hp0 = __floats2half2_rn(o0, o1);
    __half2 hp1 = __floats2half2_rn(o2, o3);
    uint2 hv;
    hv.x = *(uint32_t*)&hp0; hv.y = *(uint32_t*)&hp1;
    ((uint2*)(zh + row*Dc))[tid] = hv;
}

// ---------------------------------------------------------------------------
// Launch
// ---------------------------------------------------------------------------
extern "C" void kernel_launch(void* const* d_in, const int* in_sizes, int n_in,
                              void* d_out, int out_size)
{
    const float* x      = (const float*)d_in[0];
    const float* Wq     = (const float*)d_in[1];
    const float* Wv     = (const float*)d_in[2];
    const float* Wo     = (const float*)d_in[3];
    const float* Wg     = (const float*)d_in[4];
    const float* beta   = (const float*)d_in[5];
    const float* gamma  = (const float*)d_in[6];
    const float* lbeta  = (const float*)d_in[7];
    float* out          = (float*)d_out;

    __half *qh, *vh, *gh, *ret, *xh, *zh, *wh;
    cudaGetSymbolAddress((void**)&qh, g_qh);
    cudaGetSymbolAddress((void**)&vh, g_vh);
    cudaGetSymbolAddress((void**)&gh, g_gh);
    cudaGetSymbolAddress((void**)&ret, g_ret);
    cudaGetSymbolAddress((void**)&xh, g_xh);
    cudaGetSymbolAddress((void**)&zh, g_zh);
    cudaGetSymbolAddress((void**)&wh, g_wh);

    cudaFuncSetAttribute((const void*)gemm_mma<__half>, cudaFuncAttributeMaxDynamicSharedMemorySize, GEMM_SMEM);
    cudaFuncSetAttribute((const void*)gemm_mma<float>,  cudaFuncAttributeMaxDynamicSharedMemorySize, GEMM_SMEM);

    // Weight converts (4 weights, batched; grid sized exactly for Dc*Dc/4)
    CvtWArgs cw;
    cw.src[0] = Wq; cw.dst[0] = wh + 0*(size_t)Dc*Dc;
    cw.src[1] = Wv; cw.dst[1] = wh + 1*(size_t)Dc*Dc;
    cw.src[2] = Wg; cw.dst[2] = wh + 2*(size_t)Dc*Dc;
    cw.src[3] = Wo; cw.dst[3] = wh + 3*(size_t)Dc*Dc;
    dim3 wgrid((Dc*Dc/4 + 255)/256, 4);
    cvt_w_kernel<<<wgrid, 256>>>(cw);

    // x -> fp16
    cvt_kernel<<<(Mtot*Dc/4 + 255)/256, 256>>>(x, xh, Mtot*Dc/4);

    // Fused q/v/g projection GEMMs (fp16 outputs)
    GemmArgs<__half> a1;
    a1.Ah = xh;
    a1.Wh[0] = wh + 0*(size_t)Dc*Dc; a1.C[0] = qh;
    a1.Wh[1] = wh + 1*(size_t)Dc*Dc; a1.C[1] = vh;
    a1.Wh[2] = wh + 2*(size_t)Dc*Dc; a1.C[2] = gh;
    dim3 grid_qvg(Dc/NT, Mtot/MT, 3);   // (8, 128, 3)
    gemm_mma<__half><<<grid_qvg, 256, GEMM_SMEM>>>(a1);

    scan_pass1<<<Bc*Hc*NC, 64>>>(vh, beta);
    scan_pass2<<<(Bc*Hc*Dhc)/256, 256>>>(beta);
    scan_pass3<<<Bc*Hc*NC, 64>>>(vh, qh, ret, beta);

    ln_gate_kernel<<<Mtot, 256>>>(ret, gh, gamma, lbeta, zh);

    // Output GEMM (fp32 output)
    GemmArgs<float> a2;
    a2.Ah = zh;
    a2.Wh[0] = wh + 3*(size_t)Dc*Dc; a2.C[0] = out;
    a2.Wh[1] = a2.Wh[0]; a2.C[1] = out;
    a2.Wh[2] = a2.Wh[0]; a2.C[2] = out;
    dim3 grid_o(Dc/NT, Mtot/MT, 1);     // (8, 128, 1)
    gemm_mma<float><<<grid_o, 256, GEMM_SMEM>>>(a2);
}

// round 16
// speedup vs baseline: 1.5245x; 1.0215x over previous
#include <cuda_runtime.h>
#include <cuda_fp16.h>
#include <math.h>
#include <stdint.h>

// Problem constants
#define Bc   4
#define Lc   4096
#define Dc   1024
#define Hc   16
#define Dhc  64
#define Mtot (Bc*Lc)        // 16384 rows
#define NC   64             // scan chunks per sequence
#define CHUNK (Lc/NC)       // 64

// GEMM tiling: 128x128 tile, KT=64 k-chunk (canonical SW128), 2 CTAs/SM
#define MT 128
#define NT 128
#define KT 64               // k per stage (128 bytes/row = SW128 atom)
#define NKC (Dc/KT)         // 16 k-chunks
#define TILE_B (MT*KT*2)            // 16384 bytes per operand tile
#define OFF_AH 0
#define OFF_WH (TILE_B)
#define STAGE_BYTES (2*TILE_B)      // 32768
#define NSTAGE 3
#define GEMM_SMEM (NSTAGE*STAGE_BYTES)     // 98304 -> 2 CTAs/SM

// Canonical SW128 swizzle for 128-byte rows (verified pattern)
#define SWZ128(off) ((uint32_t)(off) ^ (((uint32_t)(off) >> 3) & 0x70u))

// ---------------------------------------------------------------------------
// Scratch (__device__ globals per allocation-free rule)
// ---------------------------------------------------------------------------
__device__ __half g_qh[Mtot*Dc];               // q (fp16)
__device__ __half g_vh[Mtot*Dc];               // v (fp16)
__device__ __half g_gh[Mtot*Dc];               // gate pre-activation (fp16)
__device__ __half g_ret[Mtot*Dc];              // ret = q*s (fp16)
__device__ float g_chunkS[Bc*Hc*NC*Dhc];       // 1 MB @ NC=64
__device__ float g_carry [Bc*Hc*NC*Dhc];
__device__ __half g_xh[Mtot*Dc];               // x in fp16
__device__ __half g_zh[Mtot*Dc];               // z in fp16
__device__ __half g_wh[4*Dc*Dc];               // Wq,Wv,Wg,Wo in fp16

// ---------------------------------------------------------------------------
// PTX helpers
// ---------------------------------------------------------------------------
__device__ __forceinline__ uint32_t smem_to_u32(const void* p) {
    uint32_t a;
    asm("{ .reg .u64 t; cvta.to.shared.u64 t, %1; cvt.u32.u64 %0, t; }" : "=r"(a) : "l"(p));
    return a;
}

#define CP16(dst, src) \
    asm volatile("cp.async.cg.shared.global [%0], [%1], 16;" :: "r"(dst), "l"(src) : "memory")

__device__ __forceinline__ void ldsm_x4(uint32_t (&r)[4], uint32_t addr) {
    asm volatile("ldmatrix.sync.aligned.m8n8.x4.shared.b16 {%0,%1,%2,%3}, [%4];"
        : "=r"(r[0]), "=r"(r[1]), "=r"(r[2]), "=r"(r[3]) : "r"(addr));
}

__device__ __forceinline__ void mma16816(float (&c)[4], const uint32_t (&a)[4],
                                         uint32_t b0, uint32_t b1) {
    asm volatile("mma.sync.aligned.m16n8k16.row.col.f32.f16.f16.f32 "
        "{%0,%1,%2,%3}, {%4,%5,%6,%7}, {%8,%9}, {%0,%1,%2,%3};"
        : "+f"(c[0]), "+f"(c[1]), "+f"(c[2]), "+f"(c[3])
        : "r"(a[0]), "r"(a[1]), "r"(a[2]), "r"(a[3]), "r"(b0), "r"(b1));
}

// ---------------------------------------------------------------------------
// Weight convert fp32 -> fp16 (batched over 4 weights)
// ---------------------------------------------------------------------------
struct CvtWArgs {
    const float* src[4];
    __half* dst[4];
};

__global__ __launch_bounds__(256)
void cvt_w_kernel(const CvtWArgs args)
{
    const int z = blockIdx.y;
    const float* s = args.src[z];
    __half* d = args.dst[z];

    int i = blockIdx.x * 256 + threadIdx.x;
    if (i >= Dc*Dc/4) return;
    float4 f = ((const float4*)s)[i];
    __half2 hp0 = __floats2half2_rn(f.x, f.y);
    __half2 hp1 = __floats2half2_rn(f.z, f.w);
    uint2 hv;
    hv.x = *(uint32_t*)&hp0; hv.y = *(uint32_t*)&hp1;
    ((uint2*)d)[i] = hv;
}

// Activation convert fp32 -> fp16
__global__ __launch_bounds__(256)
void cvt_kernel(const float* __restrict__ s, __half* __restrict__ hi, int n4)
{
    int i = blockIdx.x * 256 + threadIdx.x;
    if (i >= n4) return;
    float4 f = ((const float4*)s)[i];
    __half2 hp0 = __floats2half2_rn(f.x, f.y);
    __half2 hp1 = __floats2half2_rn(f.z, f.w);
    uint2 hv;
    hv.x = *(uint32_t*)&hp0; hv.y = *(uint32_t*)&hp1;
    ((uint2*)hi)[i] = hv;
}

// ---------------------------------------------------------------------------
// mma.sync GEMM (UNCHANGED from verified 446us config)
// ---------------------------------------------------------------------------
template <typename OutT>
struct GemmArgs {
    const __half* Ah;
    const __half* Wh[3];
    OutT* C[3];
};

template <typename OutT>
__global__ __launch_bounds__(256, 2)
void gemm_mma(const GemmArgs<OutT> args)
{
    extern __shared__ char smem[];
    const uint32_t sbase = smem_to_u32(smem);
    const int tid  = threadIdx.x;
    const int lane = tid & 31;
    const int wid  = tid >> 5;
    const int wm   = wid & 3;
    const int wn   = wid >> 2;
    const int bn   = blockIdx.x * NT;
    const int bm   = blockIdx.y * MT;
    const int z    = blockIdx.z;

    const __half* __restrict__ Ah = args.Ah;
    const __half* __restrict__ Wh = args.Wh[z];
    OutT* __restrict__ C = args.C[z];

    auto load_stage = [&](int st, int kc) {
        const uint32_t sb = sbase + (uint32_t)st * STAGE_BYTES;
        const int k0 = kc * KT;
        #pragma unroll
        for (int it = 0; it < 4; it++) {
            int idx = tid + it * 256;
            int row = idx >> 3;
            int ch  = idx & 7;
            uint32_t sw = SWZ128((uint32_t)row * 128 + (uint32_t)ch * 16);
            const __half* pa = Ah + (size_t)(bm + row) * Dc + k0 + ch * 8;
            const __half* pw = Wh + (size_t)(bn + row) * Dc + k0 + ch * 8;
            CP16(sb + OFF_AH + sw, pa);
            CP16(sb + OFF_WH + sw, pw);
        }
        asm volatile("cp.async.commit_group;" ::: "memory");
    };

    float c[2][8][4];
    #pragma unroll
    for (int i = 0; i < 2; i++)
        #pragma unroll
        for (int j = 0; j < 8; j++)
            #pragma unroll
            for (int k = 0; k < 4; k++) c[i][j][k] = 0.0f;

    load_stage(0, 0);
    load_stage(1, 1);

    const int a_r  = lane & 15;
    const int a_kc = lane >> 4;
    const int b_r  = ((lane >> 4) << 3) + (lane & 7);
    const int b_kc = (lane >> 3) & 1;

    for (int kc = 0; kc < NKC; kc++) {
        const int st = kc % NSTAGE;
        asm volatile("cp.async.wait_group 1;" ::: "memory");
        __syncthreads();

        if (kc + 2 < NKC) load_stage((kc + 2) % NSTAGE, kc + 2);
        else asm volatile("cp.async.commit_group;" ::: "memory");

        const uint32_t sb = sbase + (uint32_t)st * STAGE_BYTES;

        #pragma unroll
        for (int ks = 0; ks < 4; ks++) {
            uint32_t ah[2][4];
            #pragma unroll
            for (int mi = 0; mi < 2; mi++) {
                int row = wm * 32 + mi * 16 + a_r;
                uint32_t off = (uint32_t)row * 128 + (uint32_t)(ks * 2 + a_kc) * 16;
                ldsm_x4(ah[mi], sb + OFF_AH + SWZ128(off));
            }
            #pragma unroll
            for (int half = 0; half < 2; half++) {
                uint32_t bh[2][4];
                #pragma unroll
                for (int p = 0; p < 2; p++) {
                    int pr  = half * 2 + p;
                    int row = wn * 64 + pr * 16 + b_r;
                    uint32_t off = (uint32_t)row * 128 + (uint32_t)(ks * 2 + b_kc) * 16;
                    ldsm_x4(bh[p], sb + OFF_WH + SWZ128(off));
                }
                #pragma unroll
                for (int mi = 0; mi < 2; mi++)
                    #pragma unroll
                    for (int p = 0; p < 2; p++) {
                        int ni = (half * 2 + p) * 2;
                        mma16816(c[mi][ni+0], ah[mi], bh[p][0], bh[p][1]);
                        mma16816(c[mi][ni+1], ah[mi], bh[p][2], bh[p][3]);
                    }
            }
        }
    }

    const int er = lane >> 2;
    const int ec = (lane & 3) * 2;
    #pragma unroll
    for (int mi = 0; mi < 2; mi++) {
        #pragma unroll
        for (int ni = 0; ni < 8; ni++) {
            size_t r0g = (size_t)(bm + wm * 32 + mi * 16 + er);
            size_t cg  = (size_t)(bn + wn * 64 + ni * 8 + ec);
            if constexpr (sizeof(OutT) == 4) {
                float2* p0 = (float2*)((float*)C + r0g * Dc + cg);
                float2* p1 = (float2*)((float*)C + (r0g + 8) * Dc + cg);
                *p0 = make_float2(c[mi][ni][0], c[mi][ni][1]);
                *p1 = make_float2(c[mi][ni][2], c[mi][ni][3]);
            } else {
                __half2 h0 = __floats2half2_rn(c[mi][ni][0], c[mi][ni][1]);
                __half2 h1 = __floats2half2_rn(c[mi][ni][2], c[mi][ni][3]);
                *(__half2*)((__half*)C + r0g * Dc + cg)       = h0;
                *(__half2*)((__half*)C + (r0g + 8) * Dc + cg) = h1;
            }
        }
    }
}

// ---------------------------------------------------------------------------
// Retention scan: half2-vectorized lanes (32 lanes per chunk, 2 features/lane),
// NC=64 chunks for 2x parallelism. fp32 accumulation per feature unchanged.
// ---------------------------------------------------------------------------
__device__ __forceinline__ float lam_of(const float* beta, int h)
{
    float lam = 1.0f - exp2f(-beta[h]);
    lam = fmaxf(lam, 1.17549435e-38f);
    lam = fminf(lam, 1.0f);
    return lam;
}

// Pass 1: warp per chunk-task, 4 tasks per 128-thread block.
__global__ __launch_bounds__(128)
void scan_pass1(const __half2* __restrict__ v2, const float* __restrict__ beta)
{
    int task = blockIdx.x * 4 + (threadIdx.x >> 5);   // 0..Bc*Hc*NC-1
    int lane = threadIdx.x & 31;
    int cc  = task % NC;
    int bh  = task / NC;
    int h   = bh % Hc;
    int b   = bh / Hc;

    float lam = lam_of(beta, h);
    size_t off = (((size_t)(b*Lc + cc*CHUNK)) * Dc + h*Dhc) / 2 + lane;

    float s0 = 0.0f, s1 = 0.0f;
    #pragma unroll
    for (int t0 = 0; t0 < CHUNK; t0 += 16) {
        __half2 vals[16];
        #pragma unroll
        for (int j = 0; j < 16; j++)
            vals[j] = v2[off + (size_t)j * (Dc/2)];
        #pragma unroll
        for (int j = 0; j < 16; j++) {
            float2 f = __half22float2(vals[j]);
            s0 = fmaf(lam, s0, f.x);
            s1 = fmaf(lam, s1, f.y);
        }
        off += (size_t)16 * (Dc/2);
    }
    size_t pos = (size_t)(bh*NC + cc)*Dhc + 2*lane;
    g_chunkS[pos]   = s0;
    g_chunkS[pos+1] = s1;
}

// Pass 2: batched loads, register scan over NC=64 chunks.
__global__ __launch_bounds__(256)
void scan_pass2(const float* __restrict__ beta)
{
    int idx = blockIdx.x * blockDim.x + threadIdx.x;  // 0..4095
    int dh  = idx & 63;
    int bh  = idx >> 6;
    int h   = bh & (Hc - 1);

    float lam = lam_of(beta, h);
    float lamP = lam;
    #pragma unroll
    for (int i = 0; i < 6; i++) lamP = lamP * lamP;   // lam^64

    float cs[NC];
    #pragma unroll
    for (int cc = 0; cc < NC; cc++)
        cs[cc] = g_chunkS[(size_t)(bh*NC + cc)*Dhc + dh];

    float carry = 0.0f;
    #pragma unroll
    for (int cc = 0; cc < NC; cc++) {
        g_carry[(size_t)(bh*NC + cc)*Dhc + dh] = carry;
        carry = fmaf(lamP, carry, cs[cc]);
    }
}

// Pass 3: warp per chunk-task, half2 v/q loads, half2 ret stores.
__global__ __launch_bounds__(128)
void scan_pass3(const __half2* __restrict__ v2, const __half2* __restrict__ q2,
                __half2* __restrict__ ret2, const float* __restrict__ beta)
{
    int task = blockIdx.x * 4 + (threadIdx.x >> 5);
    int lane = threadIdx.x & 31;
    int cc  = task % NC;
    int bh  = task / NC;
    int h   = bh % Hc;
    int b   = bh / Hc;

    float lam = lam_of(beta, h);
    size_t off = (((size_t)(b*Lc + cc*CHUNK)) * Dc + h*Dhc) / 2 + lane;

    size_t cpos = (size_t)(bh*NC + cc)*Dhc + 2*lane;
    float s0 = g_carry[cpos];
    float s1 = g_carry[cpos+1];

    #pragma unroll
    for (int t0 = 0; t0 < CHUNK; t0 += 16) {
        __half2 vv[16], qq[16];
        #pragma unroll
        for (int j = 0; j < 16; j++) {
            vv[j] = v2[off + (size_t)j * (Dc/2)];
            qq[j] = q2[off + (size_t)j * (Dc/2)];
        }
        #pragma unroll
        for (int j = 0; j < 16; j++) {
            float2 fv = __half22float2(vv[j]);
            float2 fq = __half22float2(qq[j]);
            s0 = fmaf(lam, s0, fv.x);
            s1 = fmaf(lam, s1, fv.y);
            ret2[off + (size_t)j * (Dc/2)] = __floats2half2_rn(fq.x * s0, fq.y * s1);
        }
        off += (size_t)16 * (Dc/2);
    }
}

// ---------------------------------------------------------------------------
// Fused LayerNorm(ret) * SiLU(gate) -> z fp16 (fp16 in, fp32 reduce)
// ---------------------------------------------------------------------------
__global__ __launch_bounds__(256)
void ln_gate_kernel(const __half* __restrict__ ret, const __half* __restrict__ gate,
                    const float* __restrict__ gamma, const float* __restrict__ lbeta,
                    __half* __restrict__ zh)
{
    const size_t row = blockIdx.x;
    const int tid = threadIdx.x;

    uint2 rv = ((const uint2*)(ret  + row*Dc))[tid];
    uint2 gv = ((const uint2*)(gate + row*Dc))[tid];
    __half2 r01 = *(__half2*)&rv.x, r23 = *(__half2*)&rv.y;
    __half2 g01 = *(__half2*)&gv.x, g23 = *(__half2*)&gv.y;
    float r0 = __half2float(r01.x), r1 = __half2float(r01.y);
    float r2 = __half2float(r23.x), r3 = __half2float(r23.y);
    float g0 = __half2float(g01.x), g1 = __half2float(g01.y);
    float g2 = __half2float(g23.x), g3 = __half2float(g23.y);

    float s  = r0 + r1 + r2 + r3;
    float ss = r0*r0 + r1*r1 + r2*r2 + r3*r3;

    #pragma unroll
    for (int o = 16; o > 0; o >>= 1) {
        s  += __shfl_xor_sync(0xffffffffu, s,  o);
        ss += __shfl_xor_sync(0xffffffffu, ss, o);
    }
    __shared__ float shs[8], shq[8];
    if ((tid & 31) == 0) { shs[tid>>5] = s; shq[tid>>5] = ss; }
    __syncthreads();

    float tot = 0.0f, totq = 0.0f;
    #pragma unroll
    for (int i = 0; i < 8; i++) { tot += shs[i]; totq += shq[i]; }

    const float inv = 1.0f / (float)Dc;
    float mu   = tot * inv;
    float var  = totq * inv - mu * mu;
    float rstd = rsqrtf(var + 1e-5f);

    const float4 gm = ((const float4*)gamma)[tid];
    const float4 bt = ((const float4*)lbeta)[tid];

    float o0 = ((r0 - mu)*rstd*gm.x + bt.x) * (g0 / (1.0f + expf(-g0)));
    float o1 = ((r1 - mu)*rstd*gm.y + bt.y) * (g1 / (1.0f + expf(-g1)));
    float o2 = ((r2 - mu)*rstd*gm.z + bt.z) * (g2 / (1.0f + expf(-g2)));
    float o3 = ((r3 - mu)*rstd*gm.w + bt.w) * (g3 / (1.0f + expf(-g3)));

    __half2 hp0 = __floats2half2_rn(o0, o1);
    __half2 hp1 = __floats2half2_rn(o2, o3);
    uint2 hv;
    hv.x = *(uint32_t*)&hp0; hv.y = *(uint32_t*)&hp1;
    ((uint2*)(zh + row*Dc))[tid] = hv;
}

// ---------------------------------------------------------------------------
// Launch
// ---------------------------------------------------------------------------
extern "C" void kernel_launch(void* const* d_in, const int* in_sizes, int n_in,
                              void* d_out, int out_size)
{
    const float* x      = (const float*)d_in[0];
    const float* Wq     = (const float*)d_in[1];
    const float* Wv     = (const float*)d_in[2];
    const float* Wo     = (const float*)d_in[3];
    const float* Wg     = (const float*)d_in[4];
    const float* beta   = (const float*)d_in[5];
    const float* gamma  = (const float*)d_in[6];
    const float* lbeta  = (const float*)d_in[7];
    float* out          = (float*)d_out;

    __half *qh, *vh, *gh, *ret, *xh, *zh, *wh;
    cudaGetSymbolAddress((void**)&qh, g_qh);
    cudaGetSymbolAddress((void**)&vh, g_vh);
    cudaGetSymbolAddress((void**)&gh, g_gh);
    cudaGetSymbolAddress((void**)&ret, g_ret);
    cudaGetSymbolAddress((void**)&xh, g_xh);
    cudaGetSymbolAddress((void**)&zh, g_zh);
    cudaGetSymbolAddress((void**)&wh, g_wh);

    cudaFuncSetAttribute((const void*)gemm_mma<__half>, cudaFuncAttributeMaxDynamicSharedMemorySize, GEMM_SMEM);
    cudaFuncSetAttribute((const void*)gemm_mma<float>,  cudaFuncAttributeMaxDynamicSharedMemorySize, GEMM_SMEM);

    // Weight converts (4 weights, batched; exact grid)
    CvtWArgs cw;
    cw.src[0] = Wq; cw.dst[0] = wh + 0*(size_t)Dc*Dc;
    cw.src[1] = Wv; cw.dst[1] = wh + 1*(size_t)Dc*Dc;
    cw.src[2] = Wg; cw.dst[2] = wh + 2*(size_t)Dc*Dc;
    cw.src[3] = Wo; cw.dst[3] = wh + 3*(size_t)Dc*Dc;
    dim3 wgrid((Dc*Dc/4 + 255)/256, 4);
    cvt_w_kernel<<<wgrid, 256>>>(cw);

    // x -> fp16
    cvt_kernel<<<(Mtot*Dc/4 + 255)/256, 256>>>(x, xh, Mtot*Dc/4);

    // Fused q/v/g projection GEMMs (fp16 outputs)
    GemmArgs<__half> a1;
    a1.Ah = xh;
    a1.Wh[0] = wh + 0*(size_t)Dc*Dc; a1.C[0] = qh;
    a1.Wh[1] = wh + 1*(size_t)Dc*Dc; a1.C[1] = vh;
    a1.Wh[2] = wh + 2*(size_t)Dc*Dc; a1.C[2] = gh;
    dim3 grid_qvg(Dc/NT, Mtot/MT, 3);   // (8, 128, 3)
    gemm_mma<__half><<<grid_qvg, 256, GEMM_SMEM>>>(a1);

    // Scan: warp-per-chunk half2 kernels
    scan_pass1<<<(Bc*Hc*NC)/4, 128>>>((const __half2*)vh, beta);
    scan_pass2<<<(Bc*Hc*Dhc)/256, 256>>>(beta);
    scan_pass3<<<(Bc*Hc*NC)/4, 128>>>((const __half2*)vh, (const __half2*)qh,
                                      (__half2*)ret, beta);

    ln_gate_kernel<<<Mtot, 256>>>(ret, gh, gamma, lbeta, zh);

    // Output GEMM (fp32 output)
    GemmArgs<float> a2;
    a2.Ah = zh;
    a2.Wh[0] = wh + 3*(size_t)Dc*Dc; a2.C[0] = out;
    a2.Wh[1] = a2.Wh[0]; a2.C[1] = out;
    a2.Wh[2] = a2.Wh[0]; a2.C[2] = out;
    dim3 grid_o(Dc/NT, Mtot/MT, 1);     // (8, 128, 1)
    gemm_mma<float><<<grid_o, 256, GEMM_SMEM>>>(a2);
}